// round 1
// baseline (speedup 1.0000x reference)
#include <cuda_runtime.h>
#include <math_constants.h>

#define N_G   1500
#define HDIM  256
#define OUT_ELEMS (HDIM * HDIM * 3)

// Per-gaussian packed params (AoS, 8 floats each):
// [0]=k*inv00, [1]=2k*inv01, [2]=k*inv11, [3]=mx, [4]=my, [5]=cr, [6]=cg, [7]=cb
// where k = -0.5*log2(e), so splat = exp2( q2 ) with q2 <= 0.
__device__ float        g_params[N_G * 8];
__device__ unsigned int g_qmax_bits;   // uint bits of max(q2); atomicMin on bits == float max for q2<=0

__global__ void prep_kernel(const float* __restrict__ mean,
                            const float* __restrict__ alpha,
                            const float* __restrict__ scale,
                            const float* __restrict__ theta,
                            const float* __restrict__ rgb) {
    int n = blockIdx.x * blockDim.x + threadIdx.x;
    if (n == 0) g_qmax_bits = 0xFF800000u;  // -inf (largest bits among negatives)
    if (n >= N_G) return;

    const float TWO_PI = 6.283185307179586476925f;
    const float K      = -0.7213475204444817036799f;  // -0.5 * log2(e)

    float th  = theta[n];
    float sg  = 1.0f / (1.0f + expf(-th));
    float ang = sg * TWO_PI;
    float c, s;
    sincosf(ang, &s, &c);

    float sx = scale[n * 2 + 0];
    float sy = scale[n * 2 + 1];
    float sx2 = sx * sx, sy2 = sy * sy;

    float cov00 = c * c * sx2 + s * s * sy2 + 1e-6f;
    float cov01 = c * s * (sx2 - sy2);
    float cov11 = s * s * sx2 + c * c * sy2 + 1e-6f;

    float det   = cov00 * cov11 - cov01 * cov01;
    float idet  = 1.0f / det;
    float inv00 =  cov11 * idet;
    float inv01 = -cov01 * idet;
    float inv11 =  cov00 * idet;

    float mx = tanhf(mean[n * 2 + 0]) * 3.0f;
    float my = tanhf(mean[n * 2 + 1]) * 3.0f;

    float al = 1.0f / (1.0f + expf(-alpha[n]));
    float cr = (tanhf(rgb[n * 3 + 0]) * 2.0f + 1.0f) * 0.5f * al;
    float cg = (tanhf(rgb[n * 3 + 1]) * 2.0f + 1.0f) * 0.5f * al;
    float cb = (tanhf(rgb[n * 3 + 2]) * 2.0f + 1.0f) * 0.5f * al;

    float* p = &g_params[n * 8];
    p[0] = K * inv00;
    p[1] = 2.0f * K * inv01;
    p[2] = K * inv11;
    p[3] = mx;
    p[4] = my;
    p[5] = cr;
    p[6] = cg;
    p[7] = cb;
}

// One block per image row. 128 threads, each handles pixels (h, w) and (h, w+128).
__global__ void __launch_bounds__(128) splat_kernel(float* __restrict__ out) {
    __shared__ float sp[N_G * 8];
    __shared__ float warp_max[4];

    int tid = threadIdx.x;
    for (int i = tid; i < N_G * 8; i += 128)
        sp[i] = g_params[i];
    __syncthreads();

    int h = blockIdx.x;
    const float STEP = 2.0f / 255.0f;
    float py  = (h * STEP - 1.0f) * 3.0f;
    float px0 = (tid * STEP - 1.0f) * 3.0f;
    float px1 = ((tid + 128) * STEP - 1.0f) * 3.0f;

    float r0 = 0.f, g0 = 0.f, b0 = 0.f;
    float r1 = 0.f, g1 = 0.f, b1 = 0.f;
    float qmax = -CUDART_INF_F;

    #pragma unroll 4
    for (int n = 0; n < N_G; n++) {
        float4 p0 = *(const float4*)&sp[n * 8 + 0];  // A, B2, C, mx
        float4 p1 = *(const float4*)&sp[n * 8 + 4];  // my, cr, cg, cb

        float dy   = py - p1.x;
        float cdy2 = p0.z * (dy * dy);
        float bdy  = p0.y * dy;

        float dx0 = px0 - p0.w;
        float dx1 = px1 - p0.w;
        float q0  = fmaf(p0.x, dx0 * dx0, fmaf(bdy, dx0, cdy2));
        float q1  = fmaf(p0.x, dx1 * dx1, fmaf(bdy, dx1, cdy2));

        qmax = fmaxf(qmax, fmaxf(q0, q1));

        float w0, w1;
        asm("ex2.approx.ftz.f32 %0, %1;" : "=f"(w0) : "f"(q0));
        asm("ex2.approx.ftz.f32 %0, %1;" : "=f"(w1) : "f"(q1));

        r0 = fmaf(w0, p1.y, r0);
        g0 = fmaf(w0, p1.z, g0);
        b0 = fmaf(w0, p1.w, b0);
        r1 = fmaf(w1, p1.y, r1);
        g1 = fmaf(w1, p1.z, g1);
        b1 = fmaf(w1, p1.w, b1);
    }

    int base = h * HDIM;
    float* o0 = &out[(base + tid) * 3];
    float* o1 = &out[(base + tid + 128) * 3];
    o0[0] = r0; o0[1] = g0; o0[2] = b0;
    o1[0] = r1; o1[1] = g1; o1[2] = b1;

    // block max of qmax, then one atomicMin-on-bits per block (q2 <= 0 domain).
    #pragma unroll
    for (int off = 16; off > 0; off >>= 1)
        qmax = fmaxf(qmax, __shfl_xor_sync(0xFFFFFFFFu, qmax, off));
    int lane = tid & 31, wid = tid >> 5;
    if (lane == 0) warp_max[wid] = qmax;
    __syncthreads();
    if (tid == 0) {
        float m = fmaxf(fmaxf(warp_max[0], warp_max[1]),
                        fmaxf(warp_max[2], warp_max[3]));
        atomicMin(&g_qmax_bits, __float_as_uint(m));
    }
}

__global__ void finish_kernel(float* __restrict__ out) {
    int i = blockIdx.x * blockDim.x + threadIdx.x;
    if (i >= OUT_ELEMS) return;
    float qmax   = __uint_as_float(g_qmax_bits);
    float invmax = exp2f(-qmax);      // 1 / max(splat), >= 1
    float v = out[i] * invmax;
    out[i] = 1.0f / (1.0f + expf(-v));
}

extern "C" void kernel_launch(void* const* d_in, const int* in_sizes, int n_in,
                              void* d_out, int out_size) {
    const float* mean  = (const float*)d_in[0];
    const float* alpha = (const float*)d_in[1];
    const float* scale = (const float*)d_in[2];
    const float* theta = (const float*)d_in[3];
    const float* rgb   = (const float*)d_in[4];
    float* out = (float*)d_out;

    prep_kernel<<<(N_G + 255) / 256, 256>>>(mean, alpha, scale, theta, rgb);
    splat_kernel<<<HDIM, 128>>>(out);
    finish_kernel<<<(OUT_ELEMS + 255) / 256, 256>>>(out);
}

// round 2
// speedup vs baseline: 1.3215x; 1.3215x over previous
#include <cuda_runtime.h>
#include <math_constants.h>

#define N_G   1500
#define NPAIR (N_G / 2)
#define HDIM  256
#define OUT_ELEMS (HDIM * HDIM * 3)

// Pair-interleaved per-gaussian params, 16 floats per pair j (gaussians 2j, 2j+1):
// [0,1]=K*inv00      [2,3]=2K*inv01     [4,5]=K*inv11
// [6,7]=-mx          [8,9]=-my
// [10,11]=cr         [12,13]=cg         [14,15]=cb
// K = -0.5*log2(e), so splat = exp2(q2), q2 <= 0.
__device__ float        g_params[NPAIR * 16];
__device__ unsigned int g_qmax_bits;  // bits of max(q2); atomicMin-on-bits == float max for q2<=0

typedef unsigned long long u64;

__device__ __forceinline__ u64 f2add(u64 a, u64 b) {
    u64 r; asm("add.rn.f32x2 %0, %1, %2;" : "=l"(r) : "l"(a), "l"(b)); return r;
}
__device__ __forceinline__ u64 f2mul(u64 a, u64 b) {
    u64 r; asm("mul.rn.f32x2 %0, %1, %2;" : "=l"(r) : "l"(a), "l"(b)); return r;
}
__device__ __forceinline__ u64 f2fma(u64 a, u64 b, u64 c) {
    u64 r; asm("fma.rn.f32x2 %0, %1, %2, %3;" : "=l"(r) : "l"(a), "l"(b), "l"(c)); return r;
}
__device__ __forceinline__ u64 f2pack(float lo, float hi) {
    u64 r; asm("mov.b64 %0, {%1, %2};" : "=l"(r) : "f"(lo), "f"(hi)); return r;
}
__device__ __forceinline__ void f2unpack(u64 v, float& lo, float& hi) {
    asm("mov.b64 {%0, %1}, %2;" : "=f"(lo), "=f"(hi) : "l"(v));
}
__device__ __forceinline__ float fast_tanh(float x) {
    float e = __expf(2.0f * x);
    return (e - 1.0f) * __frcp_rn(e + 1.0f);
}
__device__ __forceinline__ float fast_sigmoid(float x) {
    return __frcp_rn(1.0f + __expf(-x));
}

__global__ void prep_kernel(const float* __restrict__ mean,
                            const float* __restrict__ alpha,
                            const float* __restrict__ scale,
                            const float* __restrict__ theta,
                            const float* __restrict__ rgb) {
    int n = blockIdx.x * blockDim.x + threadIdx.x;
    if (n == 0) g_qmax_bits = 0xFF800000u;  // -inf bits
    if (n >= N_G) return;

    const float TWO_PI = 6.283185307179586f;
    const float K      = -0.7213475204444817f;  // -0.5 * log2(e)

    float ang = fast_sigmoid(theta[n]) * TWO_PI;
    float s = __sinf(ang), c = __cosf(ang);

    float sx = scale[n * 2 + 0];
    float sy = scale[n * 2 + 1];
    float sx2 = sx * sx, sy2 = sy * sy;

    float cov00 = c * c * sx2 + s * s * sy2 + 1e-6f;
    float cov01 = c * s * (sx2 - sy2);
    float cov11 = s * s * sx2 + c * c * sy2 + 1e-6f;

    float det  = cov00 * cov11 - cov01 * cov01;
    float idet = __frcp_rn(det);
    float inv00 =  cov11 * idet;
    float inv01 = -cov01 * idet;
    float inv11 =  cov00 * idet;

    float mx = fast_tanh(mean[n * 2 + 0]) * 3.0f;
    float my = fast_tanh(mean[n * 2 + 1]) * 3.0f;

    float al = fast_sigmoid(alpha[n]);
    float cr = (fast_tanh(rgb[n * 3 + 0]) * 2.0f + 1.0f) * 0.5f * al;
    float cg = (fast_tanh(rgb[n * 3 + 1]) * 2.0f + 1.0f) * 0.5f * al;
    float cb = (fast_tanh(rgb[n * 3 + 2]) * 2.0f + 1.0f) * 0.5f * al;

    int j = n >> 1, o = n & 1;
    float* p = &g_params[j * 16 + o];
    p[0]  = K * inv00;
    p[2]  = 2.0f * K * inv01;
    p[4]  = K * inv11;
    p[6]  = -mx;
    p[8]  = -my;
    p[10] = cr;
    p[12] = cg;
    p[14] = cb;
}

// One block per image row, 128 threads, each handles pixels (h, tid) and (h, tid+128).
// Inner loop processes a gaussian PAIR per iteration via packed f32x2 math.
__global__ void __launch_bounds__(128) splat_kernel(float* __restrict__ out) {
    __shared__ __align__(16) float sp[NPAIR * 16];
    __shared__ float warp_max[4];

    int tid = threadIdx.x;
    {
        const float4* g4 = (const float4*)g_params;
        float4* s4 = (float4*)sp;
        for (int i = tid; i < NPAIR * 4; i += 128)
            s4[i] = g4[i];
    }
    __syncthreads();

    int h = blockIdx.x;
    const float STEP = 2.0f / 255.0f;
    float py  = (h * STEP - 1.0f) * 3.0f;
    float px0 = (tid * STEP - 1.0f) * 3.0f;
    float px1 = ((tid + 128) * STEP - 1.0f) * 3.0f;

    u64 py2  = f2pack(py, py);
    u64 px2a = f2pack(px0, px0);
    u64 px2b = f2pack(px1, px1);

    u64 ra = 0ull, ga = 0ull, ba = 0ull;   // {0.f,0.f}
    u64 rb = 0ull, gb = 0ull, bb = 0ull;
    float qm0 = -CUDART_INF_F, qm1 = -CUDART_INF_F;

    const ulonglong2* spp = (const ulonglong2*)sp;

    #pragma unroll 3
    for (int j = 0; j < NPAIR; j++) {
        ulonglong2 pA = spp[j * 4 + 0];  // {A2 , B2v}
        ulonglong2 pB = spp[j * 4 + 1];  // {C2 , nmx2}
        ulonglong2 pC = spp[j * 4 + 2];  // {nmy2, cr2}
        ulonglong2 pD = spp[j * 4 + 3];  // {cg2, cb2}

        u64 dy2  = f2add(py2, pC.x);      // py - my   (both gaussians)
        u64 dysq = f2mul(dy2, dy2);
        u64 bdy  = f2mul(pA.y, dy2);      // B*dy
        u64 cdy  = f2mul(pB.x, dysq);     // C*dy^2

        // pixel a
        u64 dxa = f2add(px2a, pB.y);
        u64 qa  = f2fma(f2fma(pA.x, dxa, bdy), dxa, cdy);
        float qa0, qa1; f2unpack(qa, qa0, qa1);
        qm0 = fmaxf(qm0, qa0);
        qm1 = fmaxf(qm1, qa1);
        float wa0, wa1;
        asm("ex2.approx.ftz.f32 %0, %1;" : "=f"(wa0) : "f"(qa0));
        asm("ex2.approx.ftz.f32 %0, %1;" : "=f"(wa1) : "f"(qa1));
        u64 wa = f2pack(wa0, wa1);
        ra = f2fma(wa, pC.y, ra);
        ga = f2fma(wa, pD.x, ga);
        ba = f2fma(wa, pD.y, ba);

        // pixel b
        u64 dxb = f2add(px2b, pB.y);
        u64 qb  = f2fma(f2fma(pA.x, dxb, bdy), dxb, cdy);
        float qb0, qb1; f2unpack(qb, qb0, qb1);
        qm0 = fmaxf(qm0, qb0);
        qm1 = fmaxf(qm1, qb1);
        float wb0, wb1;
        asm("ex2.approx.ftz.f32 %0, %1;" : "=f"(wb0) : "f"(qb0));
        asm("ex2.approx.ftz.f32 %0, %1;" : "=f"(wb1) : "f"(qb1));
        u64 wb = f2pack(wb0, wb1);
        rb = f2fma(wb, pC.y, rb);
        gb = f2fma(wb, pD.x, gb);
        bb = f2fma(wb, pD.y, bb);
    }

    // horizontal sum of gaussian-pair halves
    float t0, t1;
    int base = h * HDIM;
    float* o0 = &out[(base + tid) * 3];
    float* o1 = &out[(base + tid + 128) * 3];
    f2unpack(ra, t0, t1); o0[0] = t0 + t1;
    f2unpack(ga, t0, t1); o0[1] = t0 + t1;
    f2unpack(ba, t0, t1); o0[2] = t0 + t1;
    f2unpack(rb, t0, t1); o1[0] = t0 + t1;
    f2unpack(gb, t0, t1); o1[1] = t0 + t1;
    f2unpack(bb, t0, t1); o1[2] = t0 + t1;

    // block max of q2, one atomicMin-on-bits per block (q2 <= 0 domain)
    float qmax = fmaxf(qm0, qm1);
    #pragma unroll
    for (int off = 16; off > 0; off >>= 1)
        qmax = fmaxf(qmax, __shfl_xor_sync(0xFFFFFFFFu, qmax, off));
    int lane = tid & 31, wid = tid >> 5;
    if (lane == 0) warp_max[wid] = qmax;
    __syncthreads();
    if (tid == 0) {
        float m = fmaxf(fmaxf(warp_max[0], warp_max[1]),
                        fmaxf(warp_max[2], warp_max[3]));
        atomicMin(&g_qmax_bits, __float_as_uint(m));
    }
}

__global__ void finish_kernel(float* __restrict__ out) {
    int i = blockIdx.x * blockDim.x + threadIdx.x;
    if (i >= OUT_ELEMS) return;
    float qmax   = __uint_as_float(g_qmax_bits);
    float invmax = exp2f(-qmax);   // 1 / max(splat)
    float v = out[i] * invmax;
    out[i] = __frcp_rn(1.0f + __expf(-v));
}

extern "C" void kernel_launch(void* const* d_in, const int* in_sizes, int n_in,
                              void* d_out, int out_size) {
    const float* mean  = (const float*)d_in[0];
    const float* alpha = (const float*)d_in[1];
    const float* scale = (const float*)d_in[2];
    const float* theta = (const float*)d_in[3];
    const float* rgb   = (const float*)d_in[4];
    float* out = (float*)d_out;

    prep_kernel<<<12, 128>>>(mean, alpha, scale, theta, rgb);
    splat_kernel<<<HDIM, 128>>>(out);
    finish_kernel<<<(OUT_ELEMS + 255) / 256, 256>>>(out);
}

// round 3
// speedup vs baseline: 1.4396x; 1.0893x over previous
#include <cuda_runtime.h>
#include <math_constants.h>

#define N_G   1500
#define NPAIR (N_G / 2)           // 750
#define CHUNKS 2
#define PPC   (NPAIR / CHUNKS)    // 375 pairs per chunk
#define HDIM  256
#define OUT_ELEMS (HDIM * HDIM * 3)

// Pair-interleaved per-gaussian params, 16 floats per pair j (gaussians 2j, 2j+1):
// [0,1]=K*inv00  [2,3]=2K*inv01  [4,5]=K*inv11  [6,7]=-mx  [8,9]=-my
// [10,11]=cr     [12,13]=cg      [14,15]=cb
// K = -0.5*log2(e), so splat = exp2(q2), q2 <= 0.
__device__ float        g_params[NPAIR * 16];
__device__ float        g_part[OUT_ELEMS];    // partial sums from chunk 1
__device__ unsigned int g_qmax_bits;          // bits of max(q2); atomicMin-on-bits == float max (q2<=0)

typedef unsigned long long u64;

__device__ __forceinline__ u64 f2add(u64 a, u64 b) {
    u64 r; asm("add.rn.f32x2 %0, %1, %2;" : "=l"(r) : "l"(a), "l"(b)); return r;
}
__device__ __forceinline__ u64 f2mul(u64 a, u64 b) {
    u64 r; asm("mul.rn.f32x2 %0, %1, %2;" : "=l"(r) : "l"(a), "l"(b)); return r;
}
__device__ __forceinline__ u64 f2fma(u64 a, u64 b, u64 c) {
    u64 r; asm("fma.rn.f32x2 %0, %1, %2, %3;" : "=l"(r) : "l"(a), "l"(b), "l"(c)); return r;
}
__device__ __forceinline__ u64 f2pack(float lo, float hi) {
    u64 r; asm("mov.b64 %0, {%1, %2};" : "=l"(r) : "f"(lo), "f"(hi)); return r;
}
__device__ __forceinline__ void f2unpack(u64 v, float& lo, float& hi) {
    asm("mov.b64 {%0, %1}, %2;" : "=f"(lo), "=f"(hi) : "l"(v));
}
__device__ __forceinline__ float fast_tanh(float x) {
    float e = __expf(2.0f * x);
    return (e - 1.0f) * __frcp_rn(e + 1.0f);
}
__device__ __forceinline__ float fast_sigmoid(float x) {
    return __frcp_rn(1.0f + __expf(-x));
}

__global__ void prep_kernel(const float* __restrict__ mean,
                            const float* __restrict__ alpha,
                            const float* __restrict__ scale,
                            const float* __restrict__ theta,
                            const float* __restrict__ rgb) {
    int n = blockIdx.x * blockDim.x + threadIdx.x;
    if (n == 0) g_qmax_bits = 0xFF800000u;  // -inf bits
    if (n >= N_G) return;

    const float TWO_PI = 6.283185307179586f;
    const float K      = -0.7213475204444817f;  // -0.5 * log2(e)

    float ang = fast_sigmoid(theta[n]) * TWO_PI;
    float s = __sinf(ang), c = __cosf(ang);

    float sx = scale[n * 2 + 0];
    float sy = scale[n * 2 + 1];
    float sx2 = sx * sx, sy2 = sy * sy;

    float cov00 = c * c * sx2 + s * s * sy2 + 1e-6f;
    float cov01 = c * s * (sx2 - sy2);
    float cov11 = s * s * sx2 + c * c * sy2 + 1e-6f;

    float det  = cov00 * cov11 - cov01 * cov01;
    float idet = __frcp_rn(det);
    float inv00 =  cov11 * idet;
    float inv01 = -cov01 * idet;
    float inv11 =  cov00 * idet;

    float mx = fast_tanh(mean[n * 2 + 0]) * 3.0f;
    float my = fast_tanh(mean[n * 2 + 1]) * 3.0f;

    float al = fast_sigmoid(alpha[n]);
    float cr = (fast_tanh(rgb[n * 3 + 0]) * 2.0f + 1.0f) * 0.5f * al;
    float cg = (fast_tanh(rgb[n * 3 + 1]) * 2.0f + 1.0f) * 0.5f * al;
    float cb = (fast_tanh(rgb[n * 3 + 2]) * 2.0f + 1.0f) * 0.5f * al;

    int j = n >> 1, o = n & 1;
    float* p = &g_params[j * 16 + o];
    p[0]  = K * inv00;
    p[2]  = 2.0f * K * inv01;
    p[4]  = K * inv11;
    p[6]  = -mx;
    p[8]  = -my;
    p[10] = cr;
    p[12] = cg;
    p[14] = cb;
}

// Grid: 512 blocks = 256 rows x 2 gaussian-chunks. 64 threads/block.
// Each thread handles 4 pixels of one row: cols tid, tid+64, tid+128, tid+192
// (shared dy-chain). Inner loop processes one gaussian PAIR via f32x2.
__global__ void __launch_bounds__(64) splat_kernel(float* __restrict__ out) {
    __shared__ __align__(16) float sp[PPC * 16];
    __shared__ float warp_max[2];

    int tid   = threadIdx.x;
    int row   = blockIdx.x & 255;
    int chunk = blockIdx.x >> 8;

    {
        const float4* g4 = (const float4*)(g_params + chunk * PPC * 16);
        float4* s4 = (float4*)sp;
        for (int i = tid; i < PPC * 4; i += 64)
            s4[i] = g4[i];
    }
    __syncthreads();

    const float STEP = 2.0f / 255.0f;
    float py = (row * STEP - 1.0f) * 3.0f;
    u64 py2 = f2pack(py, py);

    u64 px2[4];
    #pragma unroll
    for (int k = 0; k < 4; k++) {
        float px = ((tid + 64 * k) * STEP - 1.0f) * 3.0f;
        px2[k] = f2pack(px, px);
    }

    u64 racc[4] = {0ull, 0ull, 0ull, 0ull};
    u64 gacc[4] = {0ull, 0ull, 0ull, 0ull};
    u64 bacc[4] = {0ull, 0ull, 0ull, 0ull};
    float qm0 = -CUDART_INF_F, qm1 = -CUDART_INF_F;

    const ulonglong2* spp = (const ulonglong2*)sp;

    #pragma unroll 3
    for (int j = 0; j < PPC; j++) {
        ulonglong2 pA = spp[j * 4 + 0];  // {A2 , B2}
        ulonglong2 pB = spp[j * 4 + 1];  // {C2 , nmx2}
        ulonglong2 pC = spp[j * 4 + 2];  // {nmy2, cr2}
        ulonglong2 pD = spp[j * 4 + 3];  // {cg2, cb2}

        u64 dy2  = f2add(py2, pC.x);      // py - my
        u64 dysq = f2mul(dy2, dy2);
        u64 bdy  = f2mul(pA.y, dy2);      // B*dy
        u64 cdy  = f2mul(pB.x, dysq);     // C*dy^2

        #pragma unroll
        for (int k = 0; k < 4; k++) {
            u64 dx = f2add(px2[k], pB.y);
            u64 q  = f2fma(f2fma(pA.x, dx, bdy), dx, cdy);
            float q0, q1; f2unpack(q, q0, q1);
            qm0 = fmaxf(qm0, q0);
            qm1 = fmaxf(qm1, q1);
            float w0, w1;
            asm("ex2.approx.ftz.f32 %0, %1;" : "=f"(w0) : "f"(q0));
            asm("ex2.approx.ftz.f32 %0, %1;" : "=f"(w1) : "f"(q1));
            u64 w = f2pack(w0, w1);
            racc[k] = f2fma(w, pC.y, racc[k]);
            gacc[k] = f2fma(w, pD.x, gacc[k]);
            bacc[k] = f2fma(w, pD.y, bacc[k]);
        }
    }

    float* dst = (chunk == 0) ? out : g_part;
    #pragma unroll
    for (int k = 0; k < 4; k++) {
        int col = tid + 64 * k;
        float* o = &dst[(row * HDIM + col) * 3];
        float t0, t1;
        f2unpack(racc[k], t0, t1); o[0] = t0 + t1;
        f2unpack(gacc[k], t0, t1); o[1] = t0 + t1;
        f2unpack(bacc[k], t0, t1); o[2] = t0 + t1;
    }

    // block max of q2, one atomicMin-on-bits per block
    float qmax = fmaxf(qm0, qm1);
    #pragma unroll
    for (int off = 16; off > 0; off >>= 1)
        qmax = fmaxf(qmax, __shfl_xor_sync(0xFFFFFFFFu, qmax, off));
    int lane = tid & 31, wid = tid >> 5;
    if (lane == 0) warp_max[wid] = qmax;
    __syncthreads();
    if (tid == 0) {
        float m = fmaxf(warp_max[0], warp_max[1]);
        atomicMin(&g_qmax_bits, __float_as_uint(m));
    }
}

__global__ void finish_kernel(float* __restrict__ out) {
    int i = blockIdx.x * blockDim.x + threadIdx.x;
    if (i >= OUT_ELEMS) return;
    float qmax   = __uint_as_float(g_qmax_bits);
    float invmax = exp2f(-qmax);   // 1 / max(splat)
    float v = (out[i] + g_part[i]) * invmax;
    out[i] = __frcp_rn(1.0f + __expf(-v));
}

extern "C" void kernel_launch(void* const* d_in, const int* in_sizes, int n_in,
                              void* d_out, int out_size) {
    const float* mean  = (const float*)d_in[0];
    const float* alpha = (const float*)d_in[1];
    const float* scale = (const float*)d_in[2];
    const float* theta = (const float*)d_in[3];
    const float* rgb   = (const float*)d_in[4];
    float* out = (float*)d_out;

    prep_kernel<<<12, 128>>>(mean, alpha, scale, theta, rgb);
    splat_kernel<<<HDIM * CHUNKS, 64>>>(out);
    finish_kernel<<<(OUT_ELEMS + 255) / 256, 256>>>(out);
}

// round 4
// speedup vs baseline: 1.5054x; 1.0457x over previous
#include <cuda_runtime.h>
#include <math_constants.h>

#define N_G     1500
#define N_G_PAD 1504
#define NPAIR   (N_G_PAD / 2)      // 752
#define CHUNKS  4
#define PPC     (NPAIR / CHUNKS)   // 188 pairs per chunk
#define HDIM    256
#define OUT_ELEMS (HDIM * HDIM * 3)

// Pair-interleaved per-gaussian params, 16 floats per pair j (gaussians 2j, 2j+1):
// [0,1]=A'=K*inv00  [2,3]=B'=2K*inv01  [4,5]=C'=K*inv11  [6,7]=-mx  [8,9]=-my
// [10,11]=cr  [12,13]=cg  [14,15]=cb        K = -0.5*log2(e)  =>  splat = exp2(q2), q2<=0
__device__ float        g_params[NPAIR * 16];
__device__ float        g_part[(CHUNKS - 1) * OUT_ELEMS];
__device__ unsigned int g_qmax_bits = 0xFF800000u;  // -inf bits; RED.MIN-on-bits == float max (q2<=0)

typedef unsigned long long u64;

__device__ __forceinline__ u64 f2add(u64 a, u64 b) {
    u64 r; asm("add.rn.f32x2 %0, %1, %2;" : "=l"(r) : "l"(a), "l"(b)); return r;
}
__device__ __forceinline__ u64 f2mul(u64 a, u64 b) {
    u64 r; asm("mul.rn.f32x2 %0, %1, %2;" : "=l"(r) : "l"(a), "l"(b)); return r;
}
__device__ __forceinline__ u64 f2fma(u64 a, u64 b, u64 c) {
    u64 r; asm("fma.rn.f32x2 %0, %1, %2, %3;" : "=l"(r) : "l"(a), "l"(b), "l"(c)); return r;
}
__device__ __forceinline__ u64 f2pack(float lo, float hi) {
    u64 r; asm("mov.b64 %0, {%1, %2};" : "=l"(r) : "f"(lo), "f"(hi)); return r;
}
__device__ __forceinline__ void f2unpack(u64 v, float& lo, float& hi) {
    asm("mov.b64 {%0, %1}, %2;" : "=f"(lo), "=f"(hi) : "l"(v));
}
__device__ __forceinline__ float fast_tanh(float x) {
    float e = __expf(2.0f * x);
    return (e - 1.0f) * __frcp_rn(e + 1.0f);
}
__device__ __forceinline__ float fast_sigmoid(float x) {
    return __frcp_rn(1.0f + __expf(-x));
}

// 8 threads per gaussian: each recomputes params; sub-thread 0 writes g_params;
// each scans 32 rows for the EXACT lattice max of q2 (concave in x -> bracket vertex).
__global__ void prep_kernel(const float* __restrict__ mean,
                            const float* __restrict__ alpha,
                            const float* __restrict__ scale,
                            const float* __restrict__ theta,
                            const float* __restrict__ rgb) {
    int t   = blockIdx.x * blockDim.x + threadIdx.x;
    int n   = t >> 3;
    int oct = t & 7;
    if (n >= N_G_PAD) return;

    const float TWO_PI = 6.283185307179586f;
    const float K      = -0.7213475204444817f;  // -0.5*log2(e)
    const float STEP   = 2.0f / 255.0f;

    float A, B, C, mx, my, cr = 0.f, cg = 0.f, cb = 0.f;
    if (n < N_G) {
        float ang = fast_sigmoid(theta[n]) * TWO_PI;
        float s = __sinf(ang), c = __cosf(ang);
        float sx = scale[n * 2 + 0], sy = scale[n * 2 + 1];
        float sx2 = sx * sx, sy2 = sy * sy;

        float cov00 = c * c * sx2 + s * s * sy2 + 1e-6f;
        float cov01 = c * s * (sx2 - sy2);
        float cov11 = s * s * sx2 + c * c * sy2 + 1e-6f;

        float idet = __frcp_rn(cov00 * cov11 - cov01 * cov01);
        A = K * ( cov11 * idet);
        B = 2.0f * K * (-cov01 * idet);
        C = K * ( cov00 * idet);

        mx = fast_tanh(mean[n * 2 + 0]) * 3.0f;
        my = fast_tanh(mean[n * 2 + 1]) * 3.0f;

        float al = fast_sigmoid(alpha[n]);
        cr = (fast_tanh(rgb[n * 3 + 0]) * 2.0f + 1.0f) * 0.5f * al;
        cg = (fast_tanh(rgb[n * 3 + 1]) * 2.0f + 1.0f) * 0.5f * al;
        cb = (fast_tanh(rgb[n * 3 + 2]) * 2.0f + 1.0f) * 0.5f * al;
    } else {
        A = -1.f; B = 0.f; C = -1.f; mx = 0.f; my = 0.f;  // benign pad, zero color
    }

    if (oct == 0) {
        int j = n >> 1, o = n & 1;
        float* p = &g_params[j * 16 + o];
        p[0] = A; p[2] = B; p[4] = C; p[6] = -mx; p[8] = -my;
        p[10] = cr; p[12] = cg; p[14] = cb;
    }

    // exact lattice max of q2 over rows [oct*32, oct*32+32)
    float qbest = -CUDART_INF_F;
    if (n < N_G) {
        float nb2a = -B * 0.5f * __frcp_rn(A);   // vertex slope: x* = nb2a * dy
        #pragma unroll 4
        for (int r = 0; r < 32; r++) {
            int row = oct * 32 + r;
            float py = (row * STEP - 1.0f) * 3.0f;
            float dy = py - my;
            float ct = C * dy * dy;
            float bd = B * dy;
            float xs = nb2a * dy;                       // continuous argmax
            float tt = fmaf(xs, 42.5f, 127.5f);         // to lattice index
            float i0 = fminf(fmaxf(floorf(tt), 0.0f), 255.0f);
            float i1 = fminf(i0 + 1.0f, 255.0f);
            float x0 = (i0 * STEP - 1.0f) * 3.0f;
            float x1 = (i1 * STEP - 1.0f) * 3.0f;
            float d0 = x0 - mx, d1 = x1 - mx;
            float q0 = fmaf(fmaf(A, d0, bd), d0, ct);
            float q1 = fmaf(fmaf(A, d1, bd), d1, ct);
            qbest = fmaxf(qbest, fmaxf(q0, q1));
        }
    }
    // warp-reduce max, one RED per warp
    #pragma unroll
    for (int off = 16; off > 0; off >>= 1)
        qbest = fmaxf(qbest, __shfl_xor_sync(0xFFFFFFFFu, qbest, off));
    if ((threadIdx.x & 31) == 0)
        atomicMin(&g_qmax_bits, __float_as_uint(qbest));  // no return use -> RED
}

// Grid: 1024 blocks = 256 rows x 4 gaussian-chunks. 64 threads.
// Thread handles 4 pixels of one row (cols tid+64k); pair of gaussians per iter via f32x2.
__global__ void __launch_bounds__(64) splat_kernel(float* __restrict__ out) {
    __shared__ __align__(16) float sp[PPC * 16];

    int tid   = threadIdx.x;
    int row   = blockIdx.x & 255;
    int chunk = blockIdx.x >> 8;

    {
        const float4* g4 = (const float4*)(g_params + chunk * PPC * 16);
        float4* s4 = (float4*)sp;
        for (int i = tid; i < PPC * 4; i += 64)
            s4[i] = g4[i];
    }
    __syncthreads();

    const float STEP = 2.0f / 255.0f;
    float py = (row * STEP - 1.0f) * 3.0f;
    u64 py2 = f2pack(py, py);

    u64 px2[4];
    #pragma unroll
    for (int k = 0; k < 4; k++) {
        float px = ((tid + 64 * k) * STEP - 1.0f) * 3.0f;
        px2[k] = f2pack(px, px);
    }

    u64 racc[4] = {0ull, 0ull, 0ull, 0ull};
    u64 gacc[4] = {0ull, 0ull, 0ull, 0ull};
    u64 bacc[4] = {0ull, 0ull, 0ull, 0ull};

    const ulonglong2* spp = (const ulonglong2*)sp;

    #pragma unroll 4
    for (int j = 0; j < PPC; j++) {
        ulonglong2 pA = spp[j * 4 + 0];  // {A2 , B2}
        ulonglong2 pB = spp[j * 4 + 1];  // {C2 , nmx2}
        ulonglong2 pC = spp[j * 4 + 2];  // {nmy2, cr2}
        ulonglong2 pD = spp[j * 4 + 3];  // {cg2, cb2}

        u64 dy2  = f2add(py2, pC.x);
        u64 dysq = f2mul(dy2, dy2);
        u64 bdy  = f2mul(pA.y, dy2);
        u64 cdy  = f2mul(pB.x, dysq);

        #pragma unroll
        for (int k = 0; k < 4; k++) {
            u64 dx = f2add(px2[k], pB.y);
            u64 q  = f2fma(f2fma(pA.x, dx, bdy), dx, cdy);
            float q0, q1; f2unpack(q, q0, q1);
            float w0, w1;
            asm("ex2.approx.ftz.f32 %0, %1;" : "=f"(w0) : "f"(q0));
            asm("ex2.approx.ftz.f32 %0, %1;" : "=f"(w1) : "f"(q1));
            u64 w = f2pack(w0, w1);
            racc[k] = f2fma(w, pC.y, racc[k]);
            gacc[k] = f2fma(w, pD.x, gacc[k]);
            bacc[k] = f2fma(w, pD.y, bacc[k]);
        }
    }

    float* dst = (chunk == 0) ? out : (g_part + (chunk - 1) * OUT_ELEMS);
    #pragma unroll
    for (int k = 0; k < 4; k++) {
        int col = tid + 64 * k;
        float* o = &dst[(row * HDIM + col) * 3];
        float t0, t1;
        f2unpack(racc[k], t0, t1); o[0] = t0 + t1;
        f2unpack(gacc[k], t0, t1); o[1] = t0 + t1;
        f2unpack(bacc[k], t0, t1); o[2] = t0 + t1;
    }
}

__global__ void finish_kernel(float* __restrict__ out) {
    int i = blockIdx.x * blockDim.x + threadIdx.x;
    if (i >= OUT_ELEMS) return;
    float qmax   = __uint_as_float(g_qmax_bits);
    float invmax = exp2f(-qmax);   // 1 / max(splat)
    float v = out[i] + g_part[i] + g_part[OUT_ELEMS + i] + g_part[2 * OUT_ELEMS + i];
    v *= invmax;
    out[i] = __frcp_rn(1.0f + __expf(-v));
}

extern "C" void kernel_launch(void* const* d_in, const int* in_sizes, int n_in,
                              void* d_out, int out_size) {
    const float* mean  = (const float*)d_in[0];
    const float* alpha = (const float*)d_in[1];
    const float* scale = (const float*)d_in[2];
    const float* theta = (const float*)d_in[3];
    const float* rgb   = (const float*)d_in[4];
    float* out = (float*)d_out;

    prep_kernel<<<(N_G_PAD * 8 + 127) / 128, 128>>>(mean, alpha, scale, theta, rgb);
    splat_kernel<<<HDIM * CHUNKS, 64>>>(out);
    finish_kernel<<<(OUT_ELEMS + 255) / 256, 256>>>(out);
}

// round 5
// speedup vs baseline: 1.5675x; 1.0413x over previous
#include <cuda_runtime.h>
#include <math_constants.h>

#define N_G     1500
#define N_G_PAD 1504
#define NPAIR   (N_G_PAD / 2)      // 752
#define CHUNKS  8
#define PPC     (NPAIR / CHUNKS)   // 94 pairs per chunk
#define HDIM    256
#define OUT_ELEMS (HDIM * HDIM * 3)
#define BIAS    110.0f
#define UNSAFE_T 160.0f

// Per-pair record: 24 floats (pair-interleaved, gaussians 2j,2j+1):
// [0,1]=A  [2,3]=B  [4,5]=C  [6,7]=-mx  [8,9]=-my
// [10,11]=P=2Ah  [12,13]=Q=Ah^2  [14,15]=R=Bh  [16,17]=rho=2^{2Ah^2}
// [18,19]=cr  [20,21]=cg  [22,23]=cb
// A=K*inv00, B=2K*inv01, C=K*inv11, K=-0.5*log2(e): splat = 2^q, q<=0.
__device__ float        g_params[NPAIR * 24];
__device__ float        g_flags[N_G_PAD];     // 0 = safe for recurrence
__device__ float        g_part[(CHUNKS - 1) * OUT_ELEMS];
__device__ unsigned int g_qmax_bits = 0xFF800000u;  // -inf; RED.MIN-on-bits == float max (q<=0)

typedef unsigned long long u64;

__device__ __forceinline__ u64 f2add(u64 a, u64 b) {
    u64 r; asm("add.rn.f32x2 %0, %1, %2;" : "=l"(r) : "l"(a), "l"(b)); return r;
}
__device__ __forceinline__ u64 f2mul(u64 a, u64 b) {
    u64 r; asm("mul.rn.f32x2 %0, %1, %2;" : "=l"(r) : "l"(a), "l"(b)); return r;
}
__device__ __forceinline__ u64 f2fma(u64 a, u64 b, u64 c) {
    u64 r; asm("fma.rn.f32x2 %0, %1, %2, %3;" : "=l"(r) : "l"(a), "l"(b), "l"(c)); return r;
}
__device__ __forceinline__ u64 f2pack(float lo, float hi) {
    u64 r; asm("mov.b64 %0, {%1, %2};" : "=l"(r) : "f"(lo), "f"(hi)); return r;
}
__device__ __forceinline__ void f2unpack(u64 v, float& lo, float& hi) {
    asm("mov.b64 {%0, %1}, %2;" : "=f"(lo), "=f"(hi) : "l"(v));
}
__device__ __forceinline__ u64 f2ex2(u64 q) {
    float a, b; f2unpack(q, a, b);
    float wa, wb;
    asm("ex2.approx.ftz.f32 %0, %1;" : "=f"(wa) : "f"(a));
    asm("ex2.approx.ftz.f32 %0, %1;" : "=f"(wb) : "f"(b));
    return f2pack(wa, wb);
}
__device__ __forceinline__ float fast_tanh(float x) {
    float e = __expf(2.0f * x);
    return (e - 1.0f) * __frcp_rn(e + 1.0f);
}
__device__ __forceinline__ float fast_sigmoid(float x) {
    return __frcp_rn(1.0f + __expf(-x));
}

// 16 threads per gaussian: all recompute params; sub 0 writes record+flag;
// each scans 16 rows for the EXACT lattice max of q (concave in x).
__global__ void prep_kernel(const float* __restrict__ mean,
                            const float* __restrict__ alpha,
                            const float* __restrict__ scale,
                            const float* __restrict__ theta,
                            const float* __restrict__ rgb) {
    int t   = blockIdx.x * blockDim.x + threadIdx.x;
    int n   = t >> 4;
    int sub = t & 15;
    if (n >= N_G_PAD) return;

    const float TWO_PI = 6.283185307179586f;
    const float K      = -0.7213475204444817f;  // -0.5*log2(e)
    const float STEP   = 2.0f / 255.0f;
    const float H      = 6.0f / 255.0f;

    float A, B, C, mx, my, cr = 0.f, cg = 0.f, cb = 0.f;
    if (n < N_G) {
        float ang = fast_sigmoid(theta[n]) * TWO_PI;
        float s = __sinf(ang), c = __cosf(ang);
        float sx = scale[n * 2 + 0], sy = scale[n * 2 + 1];
        float sx2 = sx * sx, sy2 = sy * sy;

        float cov00 = c * c * sx2 + s * s * sy2 + 1e-6f;
        float cov01 = c * s * (sx2 - sy2);
        float cov11 = s * s * sx2 + c * c * sy2 + 1e-6f;

        float idet = __frcp_rn(cov00 * cov11 - cov01 * cov01);
        A = K * ( cov11 * idet);
        B = 2.0f * K * (-cov01 * idet);
        C = K * ( cov00 * idet);

        mx = fast_tanh(mean[n * 2 + 0]) * 3.0f;
        my = fast_tanh(mean[n * 2 + 1]) * 3.0f;

        float al = fast_sigmoid(alpha[n]);
        cr = (fast_tanh(rgb[n * 3 + 0]) * 2.0f + 1.0f) * 0.5f * al;
        cg = (fast_tanh(rgb[n * 3 + 1]) * 2.0f + 1.0f) * 0.5f * al;
        cb = (fast_tanh(rgb[n * 3 + 2]) * 2.0f + 1.0f) * 0.5f * al;
    } else {
        A = -1.f; B = 0.f; C = -1.f; mx = 0.f; my = 0.f;  // benign pad, zero color
    }

    if (sub == 0) {
        int j = n >> 1, o = n & 1;
        float* p = &g_params[j * 24 + o];
        p[0]  = A;  p[2]  = B;  p[4]  = C;
        p[6]  = -mx; p[8] = -my;
        p[10] = 2.0f * A * H;       // P
        p[12] = A * H * H;          // Q
        p[14] = B * H;              // R
        p[16] = exp2f(2.0f * A * H * H);  // rho (A<0 -> <=1, finite)
        p[18] = cr; p[20] = cg; p[22] = cb;
        g_flags[n] = (2.0f * fabsf(A) + fabsf(B) >= UNSAFE_T) ? 1.0f : 0.0f;
    }

    // exact lattice max of q over rows [sub*16, sub*16+16)
    float qbest = -CUDART_INF_F;
    if (n < N_G) {
        float nb2a = -B * 0.5f * __frcp_rn(A);   // vertex slope: x* = nb2a*dy
        #pragma unroll 4
        for (int r = 0; r < 16; r++) {
            int row = sub * 16 + r;
            float py = (row * STEP - 1.0f) * 3.0f;
            float dy = py - my;
            float ct = C * dy * dy;
            float bd = B * dy;
            float xs = nb2a * dy;
            float tt = fmaf(xs, 42.5f, 127.5f);
            float i0 = fminf(fmaxf(floorf(tt), 0.0f), 255.0f);
            float i1 = fminf(i0 + 1.0f, 255.0f);
            float x0 = (i0 * STEP - 1.0f) * 3.0f;
            float x1 = (i1 * STEP - 1.0f) * 3.0f;
            float d0 = x0 - mx, d1 = x1 - mx;
            float q0 = fmaf(fmaf(A, d0, bd), d0, ct);
            float q1 = fmaf(fmaf(A, d1, bd), d1, ct);
            qbest = fmaxf(qbest, fmaxf(q0, q1));
        }
    }
    #pragma unroll
    for (int off = 16; off > 0; off >>= 1)
        qbest = fmaxf(qbest, __shfl_xor_sync(0xFFFFFFFFu, qbest, off));
    if ((threadIdx.x & 31) == 0)
        atomicMin(&g_qmax_bits, __float_as_uint(qbest));
}

// Grid: 256 blocks = 8 chunks x 32 row-blocks. 256 threads = 8 warps = 8 rows.
// Each warp owns one full row; each lane owns 8 CONTIGUOUS pixels.
// Safe pairs: geometric recurrence (4 ex2 per pair-span). Unsafe: additive-q direct.
__global__ void __launch_bounds__(256) splat_kernel(float* __restrict__ out) {
    __shared__ __align__(16) float sp[PPC * 24];
    __shared__ __align__(16) float sflag[PPC * 2];

    int tid    = threadIdx.x;
    int rowblk = blockIdx.x & 31;
    int chunk  = blockIdx.x >> 5;

    {
        const float4* g4 = (const float4*)(g_params + chunk * PPC * 24);
        float4* s4 = (float4*)sp;
        for (int i = tid; i < PPC * 6; i += 256) s4[i] = g4[i];
        const float4* f4 = (const float4*)(g_flags + chunk * PPC * 2);
        float4* sf4 = (float4*)sflag;
        for (int i = tid; i < PPC / 2; i += 256) sf4[i] = f4[i];  // 94*2/4 = 47
    }
    __syncthreads();

    int warp = tid >> 5, lane = tid & 31;
    int row  = rowblk * 8 + warp;
    int x0i  = lane * 8;

    const float STEP = 2.0f / 255.0f;
    float py = (row * STEP - 1.0f) * 3.0f;
    float px = (x0i * STEP - 1.0f) * 3.0f;
    u64 py2   = f2pack(py, py);
    u64 px2   = f2pack(px, px);
    u64 H2    = f2pack(6.0f / 255.0f, 6.0f / 255.0f);
    u64 BIAS2 = f2pack(BIAS, BIAS);

    u64 racc[8], gacc[8], bacc[8];
    #pragma unroll
    for (int k = 0; k < 8; k++) { racc[k] = 0ull; gacc[k] = 0ull; bacc[k] = 0ull; }

    const ulonglong2* spp = (const ulonglong2*)sp;
    const u64* fl = (const u64*)sflag;

    for (int j = 0; j < PPC; j++) {
        ulonglong2 p0 = spp[j * 6 + 0];  // {A, B}
        ulonglong2 p1 = spp[j * 6 + 1];  // {C, nmx}
        ulonglong2 p2 = spp[j * 6 + 2];  // {nmy, P}
        ulonglong2 p3 = spp[j * 6 + 3];  // {Q, R}
        ulonglong2 p4 = spp[j * 6 + 4];  // {rho, cr}
        ulonglong2 p5 = spp[j * 6 + 5];  // {cg, cb}

        u64 dy   = f2add(py2, p2.x);
        u64 dyq  = f2mul(dy, dy);
        u64 bdy  = f2mul(p0.y, dy);
        u64 cdyb = f2fma(p1.x, dyq, BIAS2);             // C*dy^2 + BIAS
        u64 dx0  = f2add(px2, p1.y);
        u64 q0   = f2fma(f2fma(p0.x, dx0, bdy), dx0, cdyb);
        u64 e0   = f2fma(p2.y, dx0, f2fma(p3.y, dy, p3.x));  // P*dx0 + R*dy + Q

        if (fl[j] == 0ull) {                            // warp-uniform branch
            u64 w = f2ex2(q0);
            u64 r = f2ex2(e0);
            #pragma unroll
            for (int k = 0; k < 8; k++) {
                racc[k] = f2fma(w, p4.y, racc[k]);
                gacc[k] = f2fma(w, p5.x, gacc[k]);
                bacc[k] = f2fma(w, p5.y, bacc[k]);
                w = f2mul(w, r);
                r = f2mul(r, p4.x);
            }
        } else {
            u64 t2 = f2mul(p2.y, H2);                   // 2*A*h^2
            u64 q = q0, e = e0;
            #pragma unroll
            for (int k = 0; k < 8; k++) {
                u64 w = f2ex2(q);
                racc[k] = f2fma(w, p4.y, racc[k]);
                gacc[k] = f2fma(w, p5.x, gacc[k]);
                bacc[k] = f2fma(w, p5.y, bacc[k]);
                q = f2add(q, e);
                e = f2add(e, t2);
            }
        }
    }

    float* dst = (chunk == 0) ? out : (g_part + (chunk - 1) * OUT_ELEMS);
    float* o = &dst[(row * HDIM + x0i) * 3];
    #pragma unroll
    for (int k = 0; k < 8; k++) {
        float t0, t1;
        f2unpack(racc[k], t0, t1); o[k * 3 + 0] = t0 + t1;
        f2unpack(gacc[k], t0, t1); o[k * 3 + 1] = t0 + t1;
        f2unpack(bacc[k], t0, t1); o[k * 3 + 2] = t0 + t1;
    }
}

__global__ void finish_kernel(float* __restrict__ out) {
    int i = blockIdx.x * blockDim.x + threadIdx.x;
    if (i >= OUT_ELEMS) return;
    float qmax  = __uint_as_float(g_qmax_bits);
    float scale = exp2f(-qmax - BIAS);   // un-bias + 1/max(splat)
    float v = out[i];
    #pragma unroll
    for (int c = 0; c < CHUNKS - 1; c++)
        v += g_part[c * OUT_ELEMS + i];
    v *= scale;
    out[i] = __frcp_rn(1.0f + __expf(-v));
}

extern "C" void kernel_launch(void* const* d_in, const int* in_sizes, int n_in,
                              void* d_out, int out_size) {
    const float* mean  = (const float*)d_in[0];
    const float* alpha = (const float*)d_in[1];
    const float* scale = (const float*)d_in[2];
    const float* theta = (const float*)d_in[3];
    const float* rgb   = (const float*)d_in[4];
    float* out = (float*)d_out;

    prep_kernel<<<(N_G_PAD * 16 + 127) / 128, 128>>>(mean, alpha, scale, theta, rgb);
    splat_kernel<<<32 * CHUNKS, 256>>>(out);
    finish_kernel<<<(OUT_ELEMS + 255) / 256, 256>>>(out);
}